// round 6
// baseline (speedup 1.0000x reference)
#include <cuda_runtime.h>
#include <cuda_bf16.h>
#include <math.h>
#include <stdint.h>

// ---------------- problem constants ----------------
#define G_     1024
#define H_     128
#define E_     500000
#define NN_    100000
#define K3_    384          // 3*H
#define TILE_M 128
#define KP_    392          // padded K stride (elements) for smem tiles
#define NTILES ((E_ + TILE_M - 1) / TILE_M)

// ---------------- device scratch (static, no runtime alloc) ----------------
__device__ float g_summary[G_ * H_];
__device__ float g_logz[G_];
__device__ float g_logits[E_];
__device__ float g_tmax[NN_];
__device__ float g_denom[NN_];   // after k_lse: holds lse[t] = tmax[t] + log(denom[t])
__device__ float g_lpb[G_];
__device__ float g_cnt[G_];
__device__ int   g_flags[2];                 // [0]=any byte>1 (float mode), [1]=nonzero byte at off%4!=0 (byte mode)
__device__ __nv_bfloat16 g_bw1t[H_ * K3_];   // bw1 transposed -> [n][k] bf16

// ---------------- helpers ----------------
__device__ __forceinline__ float gelu_f(float x) {
    return 0.5f * x * (1.0f + erff(x * 0.7071067811865475f));
}

__device__ __forceinline__ void atomicMaxF(float* addr, float v) {
    if (!signbit(v)) atomicMax((int*)addr, __float_as_int(v));
    else             atomicMin((unsigned int*)addr, __float_as_uint(v));
}

__device__ __forceinline__ void ldsm_x4(unsigned* r, unsigned addr) {
    asm volatile("ldmatrix.sync.aligned.m8n8.x4.shared.b16 {%0,%1,%2,%3}, [%4];\n"
                 : "=r"(r[0]), "=r"(r[1]), "=r"(r[2]), "=r"(r[3]) : "r"(addr));
}
__device__ __forceinline__ void ldsm_x2(unsigned* r, unsigned addr) {
    asm volatile("ldmatrix.sync.aligned.m8n8.x2.shared.b16 {%0,%1}, [%2];\n"
                 : "=r"(r[0]), "=r"(r[1]) : "r"(addr));
}
__device__ __forceinline__ void mma16816(float* c, const unsigned* a, const unsigned* b) {
    asm volatile("mma.sync.aligned.m16n8k16.row.col.f32.bf16.bf16.f32 "
                 "{%0,%1,%2,%3}, {%4,%5,%6,%7}, {%8,%9}, {%0,%1,%2,%3};\n"
                 : "+f"(c[0]), "+f"(c[1]), "+f"(c[2]), "+f"(c[3])
                 : "r"(a[0]), "r"(a[1]), "r"(a[2]), "r"(a[3]), "r"(b[0]), "r"(b[1]));
}

// ---------------- kernel 1: init scratch ----------------
__global__ void k_init() {
    int i = blockIdx.x * blockDim.x + threadIdx.x;
    if (i < NN_) { g_tmax[i] = -INFINITY; g_denom[i] = 0.f; }
    if (i < G_)  { g_lpb[i] = 0.f; g_cnt[i] = 0.f; }
    if (i == 0)  { g_flags[0] = 0; g_flags[1] = 0; }
}

// ---------------- kernel 2: detect selected_mask dtype ----------------
__global__ void k_detect(const unsigned* __restrict__ m) {
    const int NU = E_ / 4;   // scan first 500000 bytes as uints
    int i = blockIdx.x * blockDim.x + threadIdx.x;
    bool fa = false, fb = false;
    if (i < NU) {
        unsigned wv = m[i];
        fa = (wv & 0xFEFEFEFEu) != 0u;   // any byte > 1  -> float32 storage
        fb = (wv & 0xFFFFFF00u) != 0u;   // nonzero byte at offset%4!=0 -> uint8 storage
    }
    if (__any_sync(0xffffffffu, fa) && (threadIdx.x & 31) == 0) atomicOr(&g_flags[0], 1);
    if (__any_sync(0xffffffffu, fb) && (threadIdx.x & 31) == 0) atomicOr(&g_flags[1], 1);
}

// ---------------- kernel 3: transpose bw1 to bf16 [n][k] ----------------
__global__ void k_transpose(const float* __restrict__ bw1) {
    int i = blockIdx.x * blockDim.x + threadIdx.x;
    if (i < H_ * K3_) {
        int n = i / K3_, k = i - n * K3_;
        g_bw1t[i] = __float2bfloat16(bw1[k * H_ + n]);
    }
}

// ---------------- kernel 4: aggregate_start (segment softmax) ----------------
__global__ void k_start(const float* __restrict__ node, const float* __restrict__ q,
                        const int* __restrict__ locals, const int* __restrict__ ptr) {
    int g = blockIdx.x, j = threadIdx.x;
    __shared__ float red[128];
    __shared__ float sc[32];
    __shared__ int   nloc[32];
    int p0 = ptr[g], p1 = ptr[g + 1];
    int cnt = p1 - p0; if (cnt > 32) cnt = 32;
    if (cnt <= 0) { g_summary[g * H_ + j] = 0.f; return; }
    if (j < cnt) nloc[j] = locals[p0 + j];
    __syncthreads();
    float qj = q[g * H_ + j];
    for (int s = 0; s < cnt; s++) {
        red[j] = node[(size_t)nloc[s] * H_ + j] * qj;
        __syncthreads();
        for (int o = 64; o > 0; o >>= 1) { if (j < o) red[j] += red[j + o]; __syncthreads(); }
        if (j == 0) sc[s] = red[0] * 0.08838834764831845f;  // /sqrt(128)
        __syncthreads();
    }
    float m = -INFINITY;
    for (int s = 0; s < cnt; s++) m = fmaxf(m, sc[s]);
    float den = 0.f;
    for (int s = 0; s < cnt; s++) den += expf(sc[s] - m);
    float acc = 0.f;
    for (int s = 0; s < cnt; s++)
        acc += (expf(sc[s] - m) / den) * node[(size_t)nloc[s] * H_ + j];
    g_summary[g * H_ + j] = acc;
}

// ---------------- kernel 5: ctx_projector + log_z head ----------------
__global__ void k_ctx(const float* __restrict__ q,
                      const float* __restrict__ cw1, const float* __restrict__ cb1,
                      const float* __restrict__ cw2, const float* __restrict__ cb2,
                      const float* __restrict__ ln1g, const float* __restrict__ ln1b,
                      const float* __restrict__ zw1, const float* __restrict__ zb1,
                      const float* __restrict__ zw2, const float* __restrict__ zb2) {
    int g = blockIdx.x, j = threadIdx.x;
    __shared__ float s_in[256];
    __shared__ float sv[128];
    __shared__ float red[128];
    __shared__ float bc;
    s_in[j]       = g_summary[g * H_ + j];
    s_in[H_ + j]  = q[g * H_ + j];
    __syncthreads();
    float h = cb1[j];
    #pragma unroll 4
    for (int k = 0; k < 2 * H_; k++) h += s_in[k] * cw1[k * H_ + j];
    float a = gelu_f(h);
    sv[j] = a;
    __syncthreads();
    float ctx = cb2[j];
    #pragma unroll 4
    for (int k = 0; k < H_; k++) ctx += sv[k] * cw2[k * H_ + j];
    // LN over 128
    red[j] = ctx; __syncthreads();
    for (int o = 64; o > 0; o >>= 1) { if (j < o) red[j] += red[j + o]; __syncthreads(); }
    if (j == 0) bc = red[0];
    __syncthreads();
    float mean = bc * (1.f / 128.f);
    float d = ctx - mean;
    red[j] = d * d; __syncthreads();
    for (int o = 64; o > 0; o >>= 1) { if (j < o) red[j] += red[j + o]; __syncthreads(); }
    if (j == 0) bc = red[0];
    __syncthreads();
    float rstd = rsqrtf(bc * (1.f / 128.f) + 1e-5f);
    float xh = d * rstd * ln1g[j] + ln1b[j];
    __syncthreads();
    sv[j] = xh;
    __syncthreads();
    float z = zb1[j];
    #pragma unroll 4
    for (int k = 0; k < H_; k++) z += sv[k] * zw1[k * H_ + j];
    float gz = gelu_f(z);
    red[j] = gz * zw2[j];
    __syncthreads();
    for (int o = 64; o > 0; o >>= 1) { if (j < o) red[j] += red[j + o]; __syncthreads(); }
    if (j == 0) g_logz[g] = red[0] + zb2[0];
}

// ---------------- kernel 6: edge logits (persistent bf16 mma.sync GEMM) ----------------
// CTA: 256 threads = 8 warps, warp grid 4(M) x 2(N). Tile: 128 edges x 128 out x K=384.
// Epilogue also folds in the per-target-node atomic max (segment max for log-softmax).
__global__ __launch_bounds__(256, 1)
void k_edge(const float* __restrict__ node, const float* __restrict__ q,
            const float* __restrict__ etok,
            const float* __restrict__ blng, const float* __restrict__ blnb,
            const float* __restrict__ bb1, const float* __restrict__ bw2,
            const float* __restrict__ bb2,
            const int* __restrict__ ebatch, const int* __restrict__ eindex) {
    extern __shared__ __align__(16) unsigned char smem[];
    __nv_bfloat16* sX = (__nv_bfloat16*)smem;                 // [128][392]
    __nv_bfloat16* sW = sX + TILE_M * KP_;                    // [128][392]
    float* slog = (float*)(sW + H_ * KP_);                    // [128]
    float* sbb1 = slog + TILE_M;                              // [128]
    float* sbw2 = sbb1 + H_;                                  // [128]

    int tid = threadIdx.x;
    int w = tid >> 5, lane = tid & 31;

    // stage W^T once per CTA (bf16, padded rows)
    for (int idx = tid; idx < H_ * (K3_ / 8); idx += 256) {
        int n = idx / (K3_ / 8);
        int kk = (idx - n * (K3_ / 8)) * 8;
        *(uint4*)(&sW[n * KP_ + kk]) = *(const uint4*)(&g_bw1t[n * K3_ + kk]);
    }
    if (tid < H_) { sbb1[tid] = bb1[tid]; sbw2[tid] = bw2[tid]; }

    // per-lane LN affine params (k = lane + 32*i)
    float gk[12], bk[12];
    #pragma unroll
    for (int i = 0; i < 12; i++) { int k = lane + 32 * i; gk[i] = blng[k]; bk[i] = blnb[k]; }

    unsigned sx_u = (unsigned)__cvta_generic_to_shared(sX);
    unsigned sw_u = (unsigned)__cvta_generic_to_shared(sW);

    int wm = w & 3, wn = w >> 2;
    int a_row = wm * 32 + (lane & 15);
    int a_k   = (lane >> 4) * 8;
    int b_nl  = wn * 64 + (lane & 7);
    int b_kl  = ((lane >> 3) & 1) * 8;

    float bb2v = bb2[0];
    __syncthreads();

    for (int tile = blockIdx.x; tile < NTILES; tile += gridDim.x) {
        // ---- build LN'd X tile (each warp: 16 edges, one edge per iteration) ----
        #pragma unroll 1
        for (int r = w * 16; r < w * 16 + 16; ++r) {
            int e = tile * TILE_M + r;
            if (e < E_) {
                float x[12];
                int b = ebatch[e];
                int t = eindex[E_ + e];
                const float* pe = etok + (size_t)e * H_;
                const float* pq = q    + (size_t)b * H_;
                const float* pn = node + (size_t)t * H_;
                #pragma unroll
                for (int i = 0; i < 4; i++) x[i]     = pe[lane + 32 * i];
                #pragma unroll
                for (int i = 0; i < 4; i++) x[4 + i] = pq[lane + 32 * i];
                #pragma unroll
                for (int i = 0; i < 4; i++) x[8 + i] = pn[lane + 32 * i];
                float s = 0.f;
                #pragma unroll
                for (int i = 0; i < 12; i++) s += x[i];
                #pragma unroll
                for (int o = 16; o > 0; o >>= 1) s += __shfl_xor_sync(0xffffffffu, s, o);
                float mean = s * (1.f / 384.f);
                float vs = 0.f;
                #pragma unroll
                for (int i = 0; i < 12; i++) { float d = x[i] - mean; vs += d * d; }
                #pragma unroll
                for (int o = 16; o > 0; o >>= 1) vs += __shfl_xor_sync(0xffffffffu, vs, o);
                float rstd = rsqrtf(vs * (1.f / 384.f) + 1e-5f);
                #pragma unroll
                for (int i = 0; i < 12; i++) {
                    float xh = (x[i] - mean) * rstd * gk[i] + bk[i];
                    sX[r * KP_ + lane + 32 * i] = __float2bfloat16(xh);
                }
            } else {
                #pragma unroll
                for (int i = 0; i < 12; i++)
                    sX[r * KP_ + lane + 32 * i] = __float2bfloat16(0.f);
            }
        }
        __syncthreads();

        // ---- GEMM: [128 x 384] x [384 x 128] ----
        float c[2][8][4];
        #pragma unroll
        for (int mt = 0; mt < 2; mt++)
            #pragma unroll
            for (int nt = 0; nt < 8; nt++)
                #pragma unroll
                for (int qi = 0; qi < 4; qi++) c[mt][nt][qi] = 0.f;

        #pragma unroll 1
        for (int ks = 0; ks < K3_ / 16; ++ks) {
            int k0 = ks * 16;
            unsigned af[2][4], bf[8][2];
            #pragma unroll
            for (int mt = 0; mt < 2; mt++) {
                unsigned addr = sx_u + (unsigned)(((a_row + mt * 16) * KP_ + k0 + a_k) * 2);
                ldsm_x4(af[mt], addr);
            }
            #pragma unroll
            for (int nt = 0; nt < 8; nt++) {
                unsigned addr = sw_u + (unsigned)(((b_nl + nt * 8) * KP_ + k0 + b_kl) * 2);
                ldsm_x2(bf[nt], addr);
            }
            #pragma unroll
            for (int mt = 0; mt < 2; mt++)
                #pragma unroll
                for (int nt = 0; nt < 8; nt++)
                    mma16816(c[mt][nt], af[mt], bf[nt]);
        }

        // ---- epilogue: +bb1, erf-GELU, dot bw2, reduce per edge ----
        __syncthreads();
        if (tid < TILE_M) slog[tid] = 0.f;
        __syncthreads();
        #pragma unroll
        for (int mt = 0; mt < 2; mt++) {
            int r0 = wm * 32 + mt * 16 + (lane >> 2);
            int r1 = r0 + 8;
            float acc0 = 0.f, acc1 = 0.f;
            #pragma unroll
            for (int nt = 0; nt < 8; nt++) {
                int col = wn * 64 + nt * 8 + (lane & 3) * 2;
                float w0 = sbw2[col], w1 = sbw2[col + 1];
                float q0 = sbb1[col], q1 = sbb1[col + 1];
                acc0 += gelu_f(c[mt][nt][0] + q0) * w0 + gelu_f(c[mt][nt][1] + q1) * w1;
                acc1 += gelu_f(c[mt][nt][2] + q0) * w0 + gelu_f(c[mt][nt][3] + q1) * w1;
            }
            atomicAdd(&slog[r0], acc0);
            atomicAdd(&slog[r1], acc1);
        }
        __syncthreads();
        if (tid < TILE_M) {
            int e = tile * TILE_M + tid;
            if (e < E_) {
                float lv = slog[tid] + bb2v;
                g_logits[e] = lv;
                atomicMaxF(&g_tmax[eindex[E_ + e]], lv);   // fused segment-max
            }
        }
        __syncthreads();
    }
}

// ---------------- kernel 7: per-node exp-sum ----------------
__global__ void k_nodedenom(const int* __restrict__ eindex) {
    int e = blockIdx.x * blockDim.x + threadIdx.x;
    if (e >= E_) return;
    int t = eindex[E_ + e];
    atomicAdd(&g_denom[t], expf(g_logits[e] - g_tmax[t]));
}

// ---------------- kernel 8: fold denom into per-node lse = tmax + log(denom) ----------------
__global__ void k_lse() {
    int t = blockIdx.x * blockDim.x + threadIdx.x;
    if (t >= NN_) return;
    g_denom[t] = g_tmax[t] + logf(g_denom[t]);   // lse (safe: nodes w/o edges never read)
}

// ---------------- kernel 9: per-graph accumulation of selected log-probs ----------------
__global__ void k_accum(const int* __restrict__ eindex, const int* __restrict__ ebatch,
                        const void* __restrict__ mask) {
    int e = blockIdx.x * blockDim.x + threadIdx.x;
    if (e >= E_) return;
    bool sel;
    if (g_flags[0])      sel = (((const float*)mask)[e] != 0.f);
    else if (g_flags[1]) sel = (((const unsigned char*)mask)[e] != 0);
    else                 sel = (((const int*)mask)[e] != 0);
    if (sel) {
        int t = eindex[E_ + e];
        float lp = g_logits[e] - g_denom[t];     // logit - lse
        int b = ebatch[e];
        atomicAdd(&g_lpb[b], lp);
        atomicAdd(&g_cnt[b], 1.f);
    }
}

// ---------------- kernel 10: finalize + write output [G,3] ----------------
__global__ void k_final(float* __restrict__ out) {
    int g = threadIdx.x;   // 1024 threads
    float cnt = g_cnt[g], lpb = g_lpb[g];
    float has = cnt > 0.f ? 1.f : 0.f;
    float nll = -lpb * has;
    __shared__ float s_n[32], s_h[32];
    __shared__ float s_pb;
    float n2 = nll, h2 = has;
    #pragma unroll
    for (int o = 16; o > 0; o >>= 1) {
        n2 += __shfl_xor_sync(0xffffffffu, n2, o);
        h2 += __shfl_xor_sync(0xffffffffu, h2, o);
    }
    if ((g & 31) == 0) { s_n[g >> 5] = n2; s_h[g >> 5] = h2; }
    __syncthreads();
    if (g < 32) {
        float a = s_n[g], b = s_h[g];
        #pragma unroll
        for (int o = 16; o > 0; o >>= 1) {
            a += __shfl_xor_sync(0xffffffffu, a, o);
            b += __shfl_xor_sync(0xffffffffu, b, o);
        }
        if (g == 0) s_pb = a / fmaxf(b, 1.f);
    }
    __syncthreads();
    out[g * 3 + 0] = g_logz[g];
    out[g * 3 + 1] = lpb;
    out[g * 3 + 2] = s_pb;
}

// ---------------- launch ----------------
extern "C" void kernel_launch(void* const* d_in, const int* in_sizes, int n_in,
                              void* d_out, int out_size) {
    int I_node, I_q, I_etok, I_loc, I_ptr, I_ebatch, I_mask, I_eidx,
        I_ln1g, I_ln1b, I_zw1, I_zb1, I_zw2, I_zb2, I_cw1, I_cb1, I_cw2, I_cb2,
        I_blng, I_blnb, I_bw1, I_bb1, I_bw2, I_bb2;
    if (in_sizes[3] == 4096) {   // setup_inputs dict order
        I_node = 0;  I_q = 1;    I_etok = 2;  I_loc = 3;  I_ptr = 4;
        I_ebatch = 5; I_mask = 6; I_eidx = 7;
        I_ln1g = 8;  I_ln1b = 9; I_zw1 = 10;  I_zb1 = 11; I_zw2 = 12; I_zb2 = 13;
        I_cw1 = 14;  I_cb1 = 15; I_cw2 = 16;  I_cb2 = 17;
        I_blng = 18; I_blnb = 19; I_bw1 = 20; I_bb1 = 21; I_bw2 = 22; I_bb2 = 23;
    } else {                     // reference signature order
        I_node = 0;  I_q = 1;    I_etok = 2;
        I_ln1g = 3;  I_ln1b = 4; I_zw1 = 5;   I_zb1 = 6;  I_zw2 = 7;  I_zb2 = 8;
        I_cw1 = 9;   I_cb1 = 10; I_cw2 = 11;  I_cb2 = 12;
        I_blng = 13; I_blnb = 14; I_bw1 = 15; I_bb1 = 16; I_bw2 = 17; I_bb2 = 18;
        I_loc = 19;  I_ptr = 20; I_ebatch = 21; I_mask = 22; I_eidx = 23;
    }

    const float* node  = (const float*)d_in[I_node];
    const float* q     = (const float*)d_in[I_q];
    const float* etok  = (const float*)d_in[I_etok];
    const int*   loc   = (const int*)d_in[I_loc];
    const int*   ptr   = (const int*)d_in[I_ptr];
    const int*   ebat  = (const int*)d_in[I_ebatch];
    const int*   eidx  = (const int*)d_in[I_eidx];
    const float* ln1g  = (const float*)d_in[I_ln1g];
    const float* ln1b  = (const float*)d_in[I_ln1b];
    const float* zw1   = (const float*)d_in[I_zw1];
    const float* zb1   = (const float*)d_in[I_zb1];
    const float* zw2   = (const float*)d_in[I_zw2];
    const float* zb2   = (const float*)d_in[I_zb2];
    const float* cw1   = (const float*)d_in[I_cw1];
    const float* cb1   = (const float*)d_in[I_cb1];
    const float* cw2   = (const float*)d_in[I_cw2];
    const float* cb2   = (const float*)d_in[I_cb2];
    const float* blng  = (const float*)d_in[I_blng];
    const float* blnb  = (const float*)d_in[I_blnb];
    const float* bw1   = (const float*)d_in[I_bw1];
    const float* bb1   = (const float*)d_in[I_bb1];
    const float* bw2   = (const float*)d_in[I_bw2];
    const float* bb2   = (const float*)d_in[I_bb2];

    const int SMEM_BYTES = (TILE_M * KP_ + H_ * KP_) * 2 + (TILE_M + 2 * H_) * 4; // 202240
    cudaFuncSetAttribute(k_edge, cudaFuncAttributeMaxDynamicSharedMemorySize, SMEM_BYTES);

    k_init<<<(NN_ + 255) / 256, 256>>>();
    k_detect<<<(E_ / 4 + 255) / 256, 256>>>((const unsigned*)d_in[I_mask]);
    k_transpose<<<(H_ * K3_ + 255) / 256, 256>>>(bw1);
    k_start<<<G_, 128>>>(node, q, loc, ptr);
    k_ctx<<<G_, 128>>>(q, cw1, cb1, cw2, cb2, ln1g, ln1b, zw1, zb1, zw2, zb2);
    k_edge<<<152, 256, SMEM_BYTES>>>(node, q, etok, blng, blnb, bb1, bw2, bb2, ebat, eidx);
    k_nodedenom<<<(E_ + 255) / 256, 256>>>(eidx);
    k_lse<<<(NN_ + 255) / 256, 256>>>();
    k_accum<<<(E_ + 255) / 256, 256>>>(eidx, ebat, d_in[I_mask]);
    k_final<<<1, 1024>>>((float*)d_out);
}

// round 9
// speedup vs baseline: 1.6404x; 1.6404x over previous
#include <cuda_runtime.h>
#include <cuda_bf16.h>
#include <math.h>
#include <stdint.h>

// ---------------- problem constants ----------------
#define G_     1024
#define H_     128
#define E_     500000
#define NN_    100000
#define K3_    384
#define KP2_   136                       // padded K stride (elements) for 128-wide smem tiles
#define NTILE_E ((E_ + 127) / 128)       // 3907
#define NTILE_N ((NN_ + 127) / 128)      // 782
#define NTILE_Q ((G_ + 127) / 128)       // 8

// ---------------- device scratch (static, no runtime alloc) ----------------
__device__ float g_summary[G_ * H_];
__device__ float g_logz[G_];
__device__ float g_logits[E_];
__device__ float g_tmax[NN_];
__device__ float g_denom[NN_];           // after k_lse: lse[t] = tmax[t] + log(denom[t])
__device__ float g_lpb[G_];
__device__ float g_cnt[G_];
__device__ int   g_flags[2];
__device__ __nv_bfloat16 g_wt[3 * 128 * 128];  // slab s: [n][k] = blng[s*128+k]*bw1[(s*128+k)*128+n]
__device__ float g_C1[H_];               // bb1[n] + sum_k blnb[k]*bw1[k][n]
__device__ float g_C2[H_];               // sum_k blng[k]*bw1[k][n]
__device__ float g_Un[(size_t)NN_ * H_]; // node-slab partial products  [t][n]
__device__ float g_Uq[G_ * H_];          // question-slab partial products [g][n]
__device__ float g_sn[NN_], g_ssn[NN_];  // per-node row sum / sumsq
__device__ float g_sq[G_],  g_ssq[G_];   // per-graph q row sum / sumsq

// ---------------- helpers ----------------
__device__ __forceinline__ float gelu_f(float x) {
    return 0.5f * x * (1.0f + erff(x * 0.7071067811865475f));
}
__device__ __forceinline__ void atomicMaxF(float* addr, float v) {
    if (!signbit(v)) atomicMax((int*)addr, __float_as_int(v));
    else             atomicMin((unsigned int*)addr, __float_as_uint(v));
}
__device__ __forceinline__ unsigned pack_bf2(float a, float b) {
    __nv_bfloat162 h = __floats2bfloat162_rn(a, b);
    return *(unsigned*)&h;
}
__device__ __forceinline__ void ldsm_x4(unsigned* r, unsigned addr) {
    asm volatile("ldmatrix.sync.aligned.m8n8.x4.shared.b16 {%0,%1,%2,%3}, [%4];\n"
                 : "=r"(r[0]), "=r"(r[1]), "=r"(r[2]), "=r"(r[3]) : "r"(addr));
}
__device__ __forceinline__ void ldsm_x2(unsigned* r, unsigned addr) {
    asm volatile("ldmatrix.sync.aligned.m8n8.x2.shared.b16 {%0,%1}, [%2];\n"
                 : "=r"(r[0]), "=r"(r[1]) : "r"(addr));
}
__device__ __forceinline__ void mma16816(float* c, const unsigned* a, const unsigned* b) {
    asm volatile("mma.sync.aligned.m16n8k16.row.col.f32.bf16.bf16.f32 "
                 "{%0,%1,%2,%3}, {%4,%5,%6,%7}, {%8,%9}, {%0,%1,%2,%3};\n"
                 : "+f"(c[0]), "+f"(c[1]), "+f"(c[2]), "+f"(c[3])
                 : "r"(a[0]), "r"(a[1]), "r"(a[2]), "r"(a[3]), "r"(b[0]), "r"(b[1]));
}

// ---------------- kernel: init scratch ----------------
__global__ void k_init() {
    int i = blockIdx.x * blockDim.x + threadIdx.x;
    if (i < NN_) { g_tmax[i] = -INFINITY; g_denom[i] = 0.f; }
    if (i < G_)  { g_lpb[i] = 0.f; g_cnt[i] = 0.f; }
    if (i == 0)  { g_flags[0] = 0; g_flags[1] = 0; }
}

// ---------------- kernel: detect selected_mask dtype ----------------
__global__ void k_detect(const unsigned* __restrict__ m) {
    const int NU = E_ / 4;
    int i = blockIdx.x * blockDim.x + threadIdx.x;
    bool fa = false, fb = false;
    if (i < NU) {
        unsigned wv = m[i];
        fa = (wv & 0xFEFEFEFEu) != 0u;
        fb = (wv & 0xFFFFFF00u) != 0u;
    }
    if (__any_sync(0xffffffffu, fa) && (threadIdx.x & 31) == 0) atomicOr(&g_flags[0], 1);
    if (__any_sync(0xffffffffu, fb) && (threadIdx.x & 31) == 0) atomicOr(&g_flags[1], 1);
}

// ---------------- kernel: build gamma-scaled transposed weight slabs ----------------
__global__ void k_prep(const float* __restrict__ bw1, const float* __restrict__ blng) {
    int i = blockIdx.x * blockDim.x + threadIdx.x;
    if (i < 3 * 128 * 128) {
        int s = i >> 14, rem = i & 16383;
        int n = rem >> 7, k = rem & 127;
        int kk = s * 128 + k;
        g_wt[i] = __float2bfloat16(blng[kk] * bw1[kk * H_ + n]);
    }
}

// ---------------- kernel: C1/C2 constants ----------------
__global__ void k_prepc(const float* __restrict__ bw1, const float* __restrict__ blng,
                        const float* __restrict__ blnb, const float* __restrict__ bb1) {
    int n = threadIdx.x;
    float c1 = bb1[n], c2 = 0.f;
    for (int k = 0; k < K3_; k++) {
        float w = bw1[k * H_ + n];
        c1 += blnb[k] * w;
        c2 += blng[k] * w;
    }
    g_C1[n] = c1; g_C2[n] = c2;
}

// ---------------- generic row GEMM: out[r][n] = in[r][:] . slab'[:,n]; also row sum/sumsq ----
// mode 0: node (g_Un, g_sn, g_ssn)   mode 1: question (g_Uq, g_sq, g_ssq)
__global__ __launch_bounds__(256)
void k_rowgemm(const float* __restrict__ in, int R, int slab, int mode) {
    extern __shared__ __align__(16) unsigned char smem[];
    __nv_bfloat16* sX = (__nv_bfloat16*)smem;          // [128][KP2_]
    __nv_bfloat16* sW = sX + 128 * KP2_;               // [128][KP2_]
    int tid = threadIdx.x, w = tid >> 5, lane = tid & 31;

    // stage slab
    for (int idx = tid; idx < 128 * 16; idx += 256) {
        int n = idx >> 4, kk = (idx & 15) << 3;
        *(uint4*)(&sW[n * KP2_ + kk]) = *(const uint4*)(&g_wt[slab * 16384 + n * 128 + kk]);
    }

    // build X tile + row sums
    int row = tid >> 1, half = tid & 1;
    int grow = blockIdx.x * 128 + row;
    float s = 0.f, ss = 0.f;
    if (grow < R) {
        const float4* p = (const float4*)(in + (size_t)grow * H_ + half * 64);
        #pragma unroll
        for (int j = 0; j < 16; j++) {
            float4 v = p[j];
            s += v.x + v.y + v.z + v.w;
            ss += v.x * v.x + v.y * v.y + v.z * v.z + v.w * v.w;
            uint2 pk; pk.x = pack_bf2(v.x, v.y); pk.y = pack_bf2(v.z, v.w);
            *(uint2*)(&sX[row * KP2_ + half * 64 + j * 4]) = pk;
        }
    } else {
        #pragma unroll
        for (int j = 0; j < 16; j++)
            *(uint2*)(&sX[row * KP2_ + half * 64 + j * 4]) = make_uint2(0u, 0u);
    }
    float so = __shfl_xor_sync(0xffffffffu, s, 1);
    float sso = __shfl_xor_sync(0xffffffffu, ss, 1);
    if (half == 0 && grow < R) {
        if (mode) { g_sq[grow] = s + so;  g_ssq[grow] = ss + sso; }
        else      { g_sn[grow] = s + so;  g_ssn[grow] = ss + sso; }
    }
    __syncthreads();

    // GEMM 128x128x128
    unsigned sx_u = (unsigned)__cvta_generic_to_shared(sX);
    unsigned sw_u = (unsigned)__cvta_generic_to_shared(sW);
    int wm = w & 3, wn = w >> 2;
    int a_row = wm * 32 + (lane & 15);
    int a_k   = (lane >> 4) * 8;
    int b_nl  = wn * 64 + (lane & 7);
    int b_kl  = ((lane >> 3) & 1) * 8;

    float c[2][8][4];
    #pragma unroll
    for (int mt = 0; mt < 2; mt++)
        #pragma unroll
        for (int nt = 0; nt < 8; nt++)
            #pragma unroll
            for (int qi = 0; qi < 4; qi++) c[mt][nt][qi] = 0.f;

    #pragma unroll
    for (int ks = 0; ks < 8; ks++) {
        int k0 = ks * 16;
        unsigned af[2][4], bf[8][2];
        #pragma unroll
        for (int mt = 0; mt < 2; mt++)
            ldsm_x4(af[mt], sx_u + (unsigned)(((a_row + mt * 16) * KP2_ + k0 + a_k) * 2));
        #pragma unroll
        for (int nt = 0; nt < 8; nt++)
            ldsm_x2(bf[nt], sw_u + (unsigned)(((b_nl + nt * 8) * KP2_ + k0 + b_kl) * 2));
        #pragma unroll
        for (int mt = 0; mt < 2; mt++)
            #pragma unroll
            for (int nt = 0; nt < 8; nt++)
                mma16816(c[mt][nt], af[mt], bf[nt]);
    }

    // store fragments
    float* out = mode ? g_Uq : g_Un;
    #pragma unroll
    for (int mt = 0; mt < 2; mt++) {
        int r0 = wm * 32 + mt * 16 + (lane >> 2);
        int r1 = r0 + 8;
        int e0 = blockIdx.x * 128 + r0, e1 = blockIdx.x * 128 + r1;
        #pragma unroll
        for (int nt = 0; nt < 8; nt++) {
            int col = wn * 64 + nt * 8 + (lane & 3) * 2;
            if (e0 < R) *(float2*)(&out[(size_t)e0 * H_ + col]) = make_float2(c[mt][nt][0], c[mt][nt][1]);
            if (e1 < R) *(float2*)(&out[(size_t)e1 * H_ + col]) = make_float2(c[mt][nt][2], c[mt][nt][3]);
        }
    }
}

// ---------------- edge GEMM + fused LN-affine epilogue + logits + segment max -------------
__global__ __launch_bounds__(256)
void k_ue(const float* __restrict__ etok,
          const float* __restrict__ bw2, const float* __restrict__ bb2,
          const int* __restrict__ ebatch, const int* __restrict__ eindex) {
    extern __shared__ __align__(16) unsigned char smem[];
    __nv_bfloat16* sX = (__nv_bfloat16*)smem;          // [128][KP2_]
    __nv_bfloat16* sW = sX + 128 * KP2_;               // [128][KP2_]
    float* sse_  = (float*)(sW + 128 * KP2_);          // row sumsq [128]
    float* sse1  = sse_ + 128;                          // row sum   [128]
    float* slog  = sse1 + 128;                          // [128]
    float* sC1   = slog + 128;                          // [128]
    float* sC2   = sC1 + 128;                           // [128]
    float* sbw2  = sC2 + 128;                           // [128]

    int tid = threadIdx.x, w = tid >> 5, lane = tid & 31;
    int tile = blockIdx.x;

    for (int idx = tid; idx < 128 * 16; idx += 256) {
        int n = idx >> 4, kk = (idx & 15) << 3;
        *(uint4*)(&sW[n * KP2_ + kk]) = *(const uint4*)(&g_wt[0 * 16384 + n * 128 + kk]);
    }
    if (tid < 128) { sC1[tid] = g_C1[tid]; sC2[tid] = g_C2[tid]; sbw2[tid] = bw2[tid]; slog[tid] = 0.f; }
    float bb2v = bb2[0];

    // build X tile from etok (streaming) + row sums
    int row = tid >> 1, half = tid & 1;
    int e = tile * 128 + row;
    float s = 0.f, ss = 0.f;
    if (e < E_) {
        const float4* p = (const float4*)(etok + (size_t)e * H_ + half * 64);
        #pragma unroll
        for (int j = 0; j < 16; j++) {
            float4 v = p[j];
            s += v.x + v.y + v.z + v.w;
            ss += v.x * v.x + v.y * v.y + v.z * v.z + v.w * v.w;
            uint2 pk; pk.x = pack_bf2(v.x, v.y); pk.y = pack_bf2(v.z, v.w);
            *(uint2*)(&sX[row * KP2_ + half * 64 + j * 4]) = pk;
        }
    } else {
        #pragma unroll
        for (int j = 0; j < 16; j++)
            *(uint2*)(&sX[row * KP2_ + half * 64 + j * 4]) = make_uint2(0u, 0u);
    }
    float so = __shfl_xor_sync(0xffffffffu, s, 1);
    float sso = __shfl_xor_sync(0xffffffffu, ss, 1);
    if (half == 0) { sse1[row] = s + so; sse_[row] = ss + sso; }
    __syncthreads();

    // GEMM 128x128x128 (etok slab)
    unsigned sx_u = (unsigned)__cvta_generic_to_shared(sX);
    unsigned sw_u = (unsigned)__cvta_generic_to_shared(sW);
    int wm = w & 3, wn = w >> 2;
    int a_row = wm * 32 + (lane & 15);
    int a_k   = (lane >> 4) * 8;
    int b_nl  = wn * 64 + (lane & 7);
    int b_kl  = ((lane >> 3) & 1) * 8;

    float c[2][8][4];
    #pragma unroll
    for (int mt = 0; mt < 2; mt++)
        #pragma unroll
        for (int nt = 0; nt < 8; nt++)
            #pragma unroll
            for (int qi = 0; qi < 4; qi++) c[mt][nt][qi] = 0.f;

    #pragma unroll
    for (int ks = 0; ks < 8; ks++) {
        int k0 = ks * 16;
        unsigned af[2][4], bf[8][2];
        #pragma unroll
        for (int mt = 0; mt < 2; mt++)
            ldsm_x4(af[mt], sx_u + (unsigned)(((a_row + mt * 16) * KP2_ + k0 + a_k) * 2));
        #pragma unroll
        for (int nt = 0; nt < 8; nt++)
            ldsm_x2(bf[nt], sw_u + (unsigned)(((b_nl + nt * 8) * KP2_ + k0 + b_kl) * 2));
        #pragma unroll
        for (int mt = 0; mt < 2; mt++)
            #pragma unroll
            for (int nt = 0; nt < 8; nt++)
                mma16816(c[mt][nt], af[mt], bf[nt]);
    }
    __syncthreads();   // slog zero visible, X/W no longer needed

    // epilogue: add Uq[b] + Un[t], LN affine, gelu, dot bw2
    const float2* Uq2 = (const float2*)g_Uq;
    const float2* Un2 = (const float2*)g_Un;
    #pragma unroll
    for (int mt = 0; mt < 2; mt++) {
        int r0 = wm * 32 + mt * 16 + (lane >> 2);
        int r1 = r0 + 8;
        int e0 = tile * 128 + r0, e1 = tile * 128 + r1;
        int ec0 = e0 < E_ ? e0 : E_ - 1;
        int ec1 = e1 < E_ ? e1 : E_ - 1;
        int b0 = ebatch[ec0], t0 = eindex[E_ + ec0];
        int b1 = ebatch[ec1], t1 = eindex[E_ + ec1];
        float mean0 = (sse1[r0] + g_sq[b0] + g_sn[t0]) * (1.f / 384.f);
        float msq0  = (sse_[r0] + g_ssq[b0] + g_ssn[t0]) * (1.f / 384.f);
        float rstd0 = rsqrtf(msq0 - mean0 * mean0 + 1e-5f);
        float mean1 = (sse1[r1] + g_sq[b1] + g_sn[t1]) * (1.f / 384.f);
        float msq1  = (sse_[r1] + g_ssq[b1] + g_ssn[t1]) * (1.f / 384.f);
        float rstd1 = rsqrtf(msq1 - mean1 * mean1 + 1e-5f);
        float acc0 = 0.f, acc1 = 0.f;
        #pragma unroll
        for (int nt = 0; nt < 8; nt++) {
            int col = wn * 64 + nt * 8 + (lane & 3) * 2;
            float c1a = sC1[col], c1b = sC1[col + 1];
            float c2a = sC2[col], c2b = sC2[col + 1];
            float w0 = sbw2[col], w1 = sbw2[col + 1];
            float2 uq0 = __ldg(&Uq2[b0 * 64 + (col >> 1)]);
            float2 un0 = __ldg(&Un2[(size_t)t0 * 64 + (col >> 1)]);
            float2 uq1 = __ldg(&Uq2[b1 * 64 + (col >> 1)]);
            float2 un1 = __ldg(&Un2[(size_t)t1 * 64 + (col >> 1)]);
            float h00 = rstd0 * (c[mt][nt][0] + uq0.x + un0.x - mean0 * c2a) + c1a;
            float h01 = rstd0 * (c[mt][nt][1] + uq0.y + un0.y - mean0 * c2b) + c1b;
            float h10 = rstd1 * (c[mt][nt][2] + uq1.x + un1.x - mean1 * c2a) + c1a;
            float h11 = rstd1 * (c[mt][nt][3] + uq1.y + un1.y - mean1 * c2b) + c1b;
            acc0 += gelu_f(h00) * w0 + gelu_f(h01) * w1;
            acc1 += gelu_f(h10) * w0 + gelu_f(h11) * w1;
        }
        atomicAdd(&slog[r0], acc0);
        atomicAdd(&slog[r1], acc1);
    }
    __syncthreads();
    if (tid < 128) {
        int ee = tile * 128 + tid;
        if (ee < E_) {
            float lv = slog[tid] + bb2v;
            g_logits[ee] = lv;
            atomicMaxF(&g_tmax[eindex[E_ + ee]], lv);  // fused segment-max
        }
    }
}

// ---------------- aggregate_start (segment softmax) ----------------
__global__ void k_start(const float* __restrict__ node, const float* __restrict__ q,
                        const int* __restrict__ locals, const int* __restrict__ ptr) {
    int g = blockIdx.x, j = threadIdx.x;
    __shared__ float red[128];
    __shared__ float sc[32];
    __shared__ int   nloc[32];
    int p0 = ptr[g], p1 = ptr[g + 1];
    int cnt = p1 - p0; if (cnt > 32) cnt = 32;
    if (cnt <= 0) { g_summary[g * H_ + j] = 0.f; return; }
    if (j < cnt) nloc[j] = locals[p0 + j];
    __syncthreads();
    float qj = q[g * H_ + j];
    for (int s = 0; s < cnt; s++) {
        red[j] = node[(size_t)nloc[s] * H_ + j] * qj;
        __syncthreads();
        for (int o = 64; o > 0; o >>= 1) { if (j < o) red[j] += red[j + o]; __syncthreads(); }
        if (j == 0) sc[s] = red[0] * 0.08838834764831845f;
        __syncthreads();
    }
    float m = -INFINITY;
    for (int s = 0; s < cnt; s++) m = fmaxf(m, sc[s]);
    float den = 0.f;
    for (int s = 0; s < cnt; s++) den += expf(sc[s] - m);
    float acc = 0.f;
    for (int s = 0; s < cnt; s++)
        acc += (expf(sc[s] - m) / den) * node[(size_t)nloc[s] * H_ + j];
    g_summary[g * H_ + j] = acc;
}

// ---------------- ctx_projector + log_z head ----------------
__global__ void k_ctx(const float* __restrict__ q,
                      const float* __restrict__ cw1, const float* __restrict__ cb1,
                      const float* __restrict__ cw2, const float* __restrict__ cb2,
                      const float* __restrict__ ln1g, const float* __restrict__ ln1b,
                      const float* __restrict__ zw1, const float* __restrict__ zb1,
                      const float* __restrict__ zw2, const float* __restrict__ zb2) {
    int g = blockIdx.x, j = threadIdx.x;
    __shared__ float s_in[256];
    __shared__ float sv[128];
    __shared__ float red[128];
    __shared__ float bc;
    s_in[j]       = g_summary[g * H_ + j];
    s_in[H_ + j]  = q[g * H_ + j];
    __syncthreads();
    float h = cb1[j];
    #pragma unroll 4
    for (int k = 0; k < 2 * H_; k++) h += s_in[k] * cw1[k * H_ + j];
    float a = gelu_f(h);
    sv[j] = a;
    __syncthreads();
    float ctx = cb2[j];
    #pragma unroll 4
    for (int k = 0; k < H_; k++) ctx += sv[k] * cw2[k * H_ + j];
    red[j] = ctx; __syncthreads();
    for (int o = 64; o > 0; o >>= 1) { if (j < o) red[j] += red[j + o]; __syncthreads(); }
    if (j == 0) bc = red[0];
    __syncthreads();
    float mean = bc * (1.f / 128.f);
    float d = ctx - mean;
    red[j] = d * d; __syncthreads();
    for (int o = 64; o > 0; o >>= 1) { if (j < o) red[j] += red[j + o]; __syncthreads(); }
    if (j == 0) bc = red[0];
    __syncthreads();
    float rstd = rsqrtf(bc * (1.f / 128.f) + 1e-5f);
    float xh = d * rstd * ln1g[j] + ln1b[j];
    __syncthreads();
    sv[j] = xh;
    __syncthreads();
    float z = zb1[j];
    #pragma unroll 4
    for (int k = 0; k < H_; k++) z += sv[k] * zw1[k * H_ + j];
    float gz = gelu_f(z);
    red[j] = gz * zw2[j];
    __syncthreads();
    for (int o = 64; o > 0; o >>= 1) { if (j < o) red[j] += red[j + o]; __syncthreads(); }
    if (j == 0) g_logz[g] = red[0] + zb2[0];
}

// ---------------- segment log-softmax denom / lse / per-graph accumulation --------------
__global__ void k_nodedenom(const int* __restrict__ eindex) {
    int e = blockIdx.x * blockDim.x + threadIdx.x;
    if (e >= E_) return;
    int t = eindex[E_ + e];
    atomicAdd(&g_denom[t], expf(g_logits[e] - g_tmax[t]));
}

__global__ void k_lse() {
    int t = blockIdx.x * blockDim.x + threadIdx.x;
    if (t >= NN_) return;
    g_denom[t] = g_tmax[t] + logf(g_denom[t]);
}

__global__ void k_accum(const int* __restrict__ eindex, const int* __restrict__ ebatch,
                        const void* __restrict__ mask) {
    int e = blockIdx.x * blockDim.x + threadIdx.x;
    if (e >= E_) return;
    bool sel;
    if (g_flags[0])      sel = (((const float*)mask)[e] != 0.f);
    else if (g_flags[1]) sel = (((const unsigned char*)mask)[e] != 0);
    else                 sel = (((const int*)mask)[e] != 0);
    if (sel) {
        int t = eindex[E_ + e];
        float lp = g_logits[e] - g_denom[t];
        int b = ebatch[e];
        atomicAdd(&g_lpb[b], lp);
        atomicAdd(&g_cnt[b], 1.f);
    }
}

// ---------------- finalize + write output [G,3] ----------------
__global__ void k_final(float* __restrict__ out) {
    int g = threadIdx.x;   // 1024 threads
    float cnt = g_cnt[g], lpb = g_lpb[g];
    float has = cnt > 0.f ? 1.f : 0.f;
    float nll = -lpb * has;
    __shared__ float s_n[32], s_h[32];
    __shared__ float s_pb;
    float n2 = nll, h2 = has;
    #pragma unroll
    for (int o = 16; o > 0; o >>= 1) {
        n2 += __shfl_xor_sync(0xffffffffu, n2, o);
        h2 += __shfl_xor_sync(0xffffffffu, h2, o);
    }
    if ((g & 31) == 0) { s_n[g >> 5] = n2; s_h[g >> 5] = h2; }
    __syncthreads();
    if (g < 32) {
        float a = s_n[g], b = s_h[g];
        #pragma unroll
        for (int o = 16; o > 0; o >>= 1) {
            a += __shfl_xor_sync(0xffffffffu, a, o);
            b += __shfl_xor_sync(0xffffffffu, b, o);
        }
        if (g == 0) s_pb = a / fmaxf(b, 1.f);
    }
    __syncthreads();
    out[g * 3 + 0] = g_logz[g];
    out[g * 3 + 1] = lpb;
    out[g * 3 + 2] = s_pb;
}

// ---------------- launch ----------------
extern "C" void kernel_launch(void* const* d_in, const int* in_sizes, int n_in,
                              void* d_out, int out_size) {
    int I_node, I_q, I_etok, I_loc, I_ptr, I_ebatch, I_mask, I_eidx,
        I_ln1g, I_ln1b, I_zw1, I_zb1, I_zw2, I_zb2, I_cw1, I_cb1, I_cw2, I_cb2,
        I_blng, I_blnb, I_bw1, I_bb1, I_bw2, I_bb2;
    if (in_sizes[3] == 4096) {   // setup_inputs dict order
        I_node = 0;  I_q = 1;    I_etok = 2;  I_loc = 3;  I_ptr = 4;
        I_ebatch = 5; I_mask = 6; I_eidx = 7;
        I_ln1g = 8;  I_ln1b = 9; I_zw1 = 10;  I_zb1 = 11; I_zw2 = 12; I_zb2 = 13;
        I_cw1 = 14;  I_cb1 = 15; I_cw2 = 16;  I_cb2 = 17;
        I_blng = 18; I_blnb = 19; I_bw1 = 20; I_bb1 = 21; I_bw2 = 22; I_bb2 = 23;
    } else {                     // reference signature order
        I_node = 0;  I_q = 1;    I_etok = 2;
        I_ln1g = 3;  I_ln1b = 4; I_zw1 = 5;   I_zb1 = 6;  I_zw2 = 7;  I_zb2 = 8;
        I_cw1 = 9;   I_cb1 = 10; I_cw2 = 11;  I_cb2 = 12;
        I_blng = 13; I_blnb = 14; I_bw1 = 15; I_bb1 = 16; I_bw2 = 17; I_bb2 = 18;
        I_loc = 19;  I_ptr = 20; I_ebatch = 21; I_mask = 22; I_eidx = 23;
    }

    const float* node  = (const float*)d_in[I_node];
    const float* q     = (const float*)d_in[I_q];
    const float* etok  = (const float*)d_in[I_etok];
    const int*   loc   = (const int*)d_in[I_loc];
    const int*   ptr   = (const int*)d_in[I_ptr];
    const int*   ebat  = (const int*)d_in[I_ebatch];
    const int*   eidx  = (const int*)d_in[I_eidx];
    const float* ln1g  = (const float*)d_in[I_ln1g];
    const float* ln1b  = (const float*)d_in[I_ln1b];
    const float* zw1   = (const float*)d_in[I_zw1];
    const float* zb1   = (const float*)d_in[I_zb1];
    const float* zw2   = (const float*)d_in[I_zw2];
    const float* zb2   = (const float*)d_in[I_zb2];
    const float* cw1   = (const float*)d_in[I_cw1];
    const float* cb1   = (const float*)d_in[I_cb1];
    const float* cw2   = (const float*)d_in[I_cw2];
    const float* cb2   = (const float*)d_in[I_cb2];
    const float* blng  = (const float*)d_in[I_blng];
    const float* blnb  = (const float*)d_in[I_blnb];
    const float* bw1   = (const float*)d_in[I_bw1];
    const float* bb1   = (const float*)d_in[I_bb1];
    const float* bw2   = (const float*)d_in[I_bw2];
    const float* bb2   = (const float*)d_in[I_bb2];

    const int SM_ROWG = 2 * 128 * KP2_ * 2;            // 69632
    const int SM_UE   = SM_ROWG + 6 * 128 * 4;         // 72704
    cudaFuncSetAttribute(k_rowgemm, cudaFuncAttributeMaxDynamicSharedMemorySize, SM_ROWG);
    cudaFuncSetAttribute(k_ue,      cudaFuncAttributeMaxDynamicSharedMemorySize, SM_UE);

    k_init<<<(NN_ + 255) / 256, 256>>>();
    k_detect<<<(E_ / 4 + 255) / 256, 256>>>((const unsigned*)d_in[I_mask]);
    k_prep<<<(3 * 128 * 128 + 255) / 256, 256>>>(bw1, blng);
    k_prepc<<<1, 128>>>(bw1, blng, blnb, bb1);
    k_rowgemm<<<NTILE_N, 256, SM_ROWG>>>(node, NN_, 2, 0);
    k_rowgemm<<<NTILE_Q, 256, SM_ROWG>>>(q, G_, 1, 1);
    k_start<<<G_, 128>>>(node, q, loc, ptr);
    k_ctx<<<G_, 128>>>(q, cw1, cb1, cw2, cb2, ln1g, ln1b, zw1, zb1, zw2, zb2);
    k_ue<<<NTILE_E, 256, SM_UE>>>(etok, bw2, bb2, ebat, eidx);
    k_nodedenom<<<(E_ + 255) / 256, 256>>>(eidx);
    k_lse<<<(NN_ + 255) / 256, 256>>>();
    k_accum<<<(E_ + 255) / 256, 256>>>(eidx, ebat, d_in[I_mask]);
    k_final<<<1, 1024>>>((float*)d_out);
}

// round 13
// speedup vs baseline: 1.7714x; 1.0798x over previous
#include <cuda_runtime.h>
#include <cuda_bf16.h>
#include <math.h>
#include <stdint.h>

// ---------------- problem constants ----------------
#define G_     1024
#define H_     128
#define E_     500000
#define NN_    100000
#define K3_    384
#define KP2_   136                       // padded K stride (elements) for 128-wide smem tiles
#define NTILE_E ((E_ + 127) / 128)       // 3907
#define NTILE_N ((NN_ + 127) / 128)      // 782
#define NTILE_Q ((G_ + 127) / 128)       // 8

// ---------------- device scratch (static, no runtime alloc) ----------------
__device__ float g_summary[G_ * H_];
__device__ float g_logz[G_];
__device__ float g_logits[E_];
__device__ float g_tmax[NN_];
__device__ float g_denom[NN_];           // after k_lse: lse[t] = tmax[t] + log(denom[t])
__device__ float g_lpb[G_];
__device__ float g_cnt[G_];
__device__ int   g_flags[2];
__device__ __nv_bfloat16 g_wt[3 * 128 * 128];  // slab s: [n][k] = blng[s*128+k]*bw1[(s*128+k)*128+n]
__device__ float g_C1[H_];               // bb1[n] + sum_k blnb[k]*bw1[k][n]
__device__ float g_C2[H_];               // sum_k blng[k]*bw1[k][n]
__device__ __nv_bfloat16 g_Un[(size_t)NN_ * H_]; // node-slab partials (bf16 to halve L2 gather traffic)
__device__ __nv_bfloat16 g_Uq[G_ * H_];          // question-slab partials (bf16)
__device__ float g_sn[NN_], g_ssn[NN_];  // per-node row sum / sumsq
__device__ float g_sq[G_],  g_ssq[G_];   // per-graph q row sum / sumsq

// ---------------- helpers ----------------
__device__ __forceinline__ float gelu_f(float x) {
    return 0.5f * x * (1.0f + erff(x * 0.7071067811865475f));
}
__device__ __forceinline__ void atomicMaxF(float* addr, float v) {
    if (!signbit(v)) atomicMax((int*)addr, __float_as_int(v));
    else             atomicMin((unsigned int*)addr, __float_as_uint(v));
}
__device__ __forceinline__ unsigned pack_bf2(float a, float b) {
    __nv_bfloat162 h = __floats2bfloat162_rn(a, b);
    return *(unsigned*)&h;
}
__device__ __forceinline__ float2 unpack_bf2(const __nv_bfloat16* p) {
    return __bfloat1622float2(*(const __nv_bfloat162*)p);
}
__device__ __forceinline__ void ldsm_x4(unsigned* r, unsigned addr) {
    asm volatile("ldmatrix.sync.aligned.m8n8.x4.shared.b16 {%0,%1,%2,%3}, [%4];\n"
                 : "=r"(r[0]), "=r"(r[1]), "=r"(r[2]), "=r"(r[3]) : "r"(addr));
}
__device__ __forceinline__ void ldsm_x2(unsigned* r, unsigned addr) {
    asm volatile("ldmatrix.sync.aligned.m8n8.x2.shared.b16 {%0,%1}, [%2];\n"
                 : "=r"(r[0]), "=r"(r[1]) : "r"(addr));
}
__device__ __forceinline__ void mma16816(float* c, const unsigned* a, const unsigned* b) {
    asm volatile("mma.sync.aligned.m16n8k16.row.col.f32.bf16.bf16.f32 "
                 "{%0,%1,%2,%3}, {%4,%5,%6,%7}, {%8,%9}, {%0,%1,%2,%3};\n"
                 : "+f"(c[0]), "+f"(c[1]), "+f"(c[2]), "+f"(c[3])
                 : "r"(a[0]), "r"(a[1]), "r"(a[2]), "r"(a[3]), "r"(b[0]), "r"(b[1]));
}

// ---------------- kernel: init scratch ----------------
__global__ void k_init() {
    int i = blockIdx.x * blockDim.x + threadIdx.x;
    if (i < NN_) { g_tmax[i] = -INFINITY; g_denom[i] = 0.f; }
    if (i < G_)  { g_lpb[i] = 0.f; g_cnt[i] = 0.f; }
    if (i == 0)  { g_flags[0] = 0; g_flags[1] = 0; }
}

// ---------------- kernel: detect selected_mask dtype ----------------
__global__ void k_detect(const unsigned* __restrict__ m) {
    const int NU = E_ / 4;
    int i = blockIdx.x * blockDim.x + threadIdx.x;
    bool fa = false, fb = false;
    if (i < NU) {
        unsigned wv = m[i];
        fa = (wv & 0xFEFEFEFEu) != 0u;
        fb = (wv & 0xFFFFFF00u) != 0u;
    }
    if (__any_sync(0xffffffffu, fa) && (threadIdx.x & 31) == 0) atomicOr(&g_flags[0], 1);
    if (__any_sync(0xffffffffu, fb) && (threadIdx.x & 31) == 0) atomicOr(&g_flags[1], 1);
}

// ---------------- kernel: build gamma-scaled transposed weight slabs ----------------
__global__ void k_prep(const float* __restrict__ bw1, const float* __restrict__ blng) {
    int i = blockIdx.x * blockDim.x + threadIdx.x;
    if (i < 3 * 128 * 128) {
        int s = i >> 14, rem = i & 16383;
        int n = rem >> 7, k = rem & 127;
        int kk = s * 128 + k;
        g_wt[i] = __float2bfloat16(blng[kk] * bw1[kk * H_ + n]);
    }
}

// ---------------- kernel: C1/C2 constants (parallel: one block per n) ----------------
__global__ void k_prepc(const float* __restrict__ bw1, const float* __restrict__ blng,
                        const float* __restrict__ blnb, const float* __restrict__ bb1) {
    int n = blockIdx.x;            // 128 blocks
    int t = threadIdx.x;           // 128 threads
    __shared__ float r1[128], r2[128];
    float c1 = 0.f, c2 = 0.f;
    #pragma unroll
    for (int kk = t; kk < K3_; kk += 128) {
        float w = bw1[kk * H_ + n];
        c1 += blnb[kk] * w;
        c2 += blng[kk] * w;
    }
    r1[t] = c1; r2[t] = c2;
    __syncthreads();
    for (int o = 64; o > 0; o >>= 1) {
        if (t < o) { r1[t] += r1[t + o]; r2[t] += r2[t + o]; }
        __syncthreads();
    }
    if (t == 0) { g_C1[n] = r1[0] + bb1[n]; g_C2[n] = r2[0]; }
}

// ---------------- generic row GEMM: out[r][n] = in[r][:] . slab'[:,n]; also row sum/sumsq ----
// mode 0: node (g_Un, g_sn, g_ssn)   mode 1: question (g_Uq, g_sq, g_ssq)
__global__ __launch_bounds__(256)
void k_rowgemm(const float* __restrict__ in, int R, int slab, int mode) {
    extern __shared__ __align__(16) unsigned char smem[];
    __nv_bfloat16* sX = (__nv_bfloat16*)smem;          // [128][KP2_]
    __nv_bfloat16* sW = sX + 128 * KP2_;               // [128][KP2_]
    int tid = threadIdx.x, w = tid >> 5, lane = tid & 31;

    // stage slab
    for (int idx = tid; idx < 128 * 16; idx += 256) {
        int n = idx >> 4, kk = (idx & 15) << 3;
        *(uint4*)(&sW[n * KP2_ + kk]) = *(const uint4*)(&g_wt[slab * 16384 + n * 128 + kk]);
    }

    // build X tile + row sums
    int row = tid >> 1, half = tid & 1;
    int grow = blockIdx.x * 128 + row;
    float s = 0.f, ss = 0.f;
    if (grow < R) {
        const float4* p = (const float4*)(in + (size_t)grow * H_ + half * 64);
        #pragma unroll
        for (int j = 0; j < 16; j++) {
            float4 v = p[j];
            s += v.x + v.y + v.z + v.w;
            ss += v.x * v.x + v.y * v.y + v.z * v.z + v.w * v.w;
            uint2 pk; pk.x = pack_bf2(v.x, v.y); pk.y = pack_bf2(v.z, v.w);
            *(uint2*)(&sX[row * KP2_ + half * 64 + j * 4]) = pk;
        }
    } else {
        #pragma unroll
        for (int j = 0; j < 16; j++)
            *(uint2*)(&sX[row * KP2_ + half * 64 + j * 4]) = make_uint2(0u, 0u);
    }
    float so = __shfl_xor_sync(0xffffffffu, s, 1);
    float sso = __shfl_xor_sync(0xffffffffu, ss, 1);
    if (half == 0 && grow < R) {
        if (mode) { g_sq[grow] = s + so;  g_ssq[grow] = ss + sso; }
        else      { g_sn[grow] = s + so;  g_ssn[grow] = ss + sso; }
    }
    __syncthreads();

    // GEMM 128x128x128
    unsigned sx_u = (unsigned)__cvta_generic_to_shared(sX);
    unsigned sw_u = (unsigned)__cvta_generic_to_shared(sW);
    int wm = w & 3, wn = w >> 2;
    int a_row = wm * 32 + (lane & 15);
    int a_k   = (lane >> 4) * 8;
    int b_nl  = wn * 64 + (lane & 7);
    int b_kl  = ((lane >> 3) & 1) * 8;

    float c[2][8][4];
    #pragma unroll
    for (int mt = 0; mt < 2; mt++)
        #pragma unroll
        for (int nt = 0; nt < 8; nt++)
            #pragma unroll
            for (int qi = 0; qi < 4; qi++) c[mt][nt][qi] = 0.f;

    #pragma unroll
    for (int ks = 0; ks < 8; ks++) {
        int k0 = ks * 16;
        unsigned af[2][4], bf[8][2];
        #pragma unroll
        for (int mt = 0; mt < 2; mt++)
            ldsm_x4(af[mt], sx_u + (unsigned)(((a_row + mt * 16) * KP2_ + k0 + a_k) * 2));
        #pragma unroll
        for (int nt = 0; nt < 8; nt++)
            ldsm_x2(bf[nt], sw_u + (unsigned)(((b_nl + nt * 8) * KP2_ + k0 + b_kl) * 2));
        #pragma unroll
        for (int mt = 0; mt < 2; mt++)
            #pragma unroll
            for (int nt = 0; nt < 8; nt++)
                mma16816(c[mt][nt], af[mt], bf[nt]);
    }

    // store fragments (bf16x2 packed)
    __nv_bfloat16* out = mode ? g_Uq : g_Un;
    #pragma unroll
    for (int mt = 0; mt < 2; mt++) {
        int r0 = wm * 32 + mt * 16 + (lane >> 2);
        int r1 = r0 + 8;
        int e0 = blockIdx.x * 128 + r0, e1 = blockIdx.x * 128 + r1;
        #pragma unroll
        for (int nt = 0; nt < 8; nt++) {
            int col = wn * 64 + nt * 8 + (lane & 3) * 2;
            if (e0 < R) *(unsigned*)(&out[(size_t)e0 * H_ + col]) = pack_bf2(c[mt][nt][0], c[mt][nt][1]);
            if (e1 < R) *(unsigned*)(&out[(size_t)e1 * H_ + col]) = pack_bf2(c[mt][nt][2], c[mt][nt][3]);
        }
    }
}

// ---------------- edge GEMM + fused LN-affine epilogue + logits + segment max -------------
__global__ __launch_bounds__(256)
void k_ue(const float* __restrict__ etok,
          const float* __restrict__ bw2, const float* __restrict__ bb2,
          const int* __restrict__ ebatch, const int* __restrict__ eindex) {
    extern __shared__ __align__(16) unsigned char smem[];
    __nv_bfloat16* sX = (__nv_bfloat16*)smem;          // [128][KP2_]
    __nv_bfloat16* sW = sX + 128 * KP2_;               // [128][KP2_]
    float* sse_  = (float*)(sW + 128 * KP2_);          // row sumsq [128]
    float* sse1  = sse_ + 128;                          // row sum   [128]
    float* slog  = sse1 + 128;                          // [128]
    float* sC1   = slog + 128;                          // [128]
    float* sC2   = sC1 + 128;                           // [128]
    float* sbw2  = sC2 + 128;                           // [128]

    int tid = threadIdx.x, w = tid >> 5, lane = tid & 31;
    int tile = blockIdx.x;

    for (int idx = tid; idx < 128 * 16; idx += 256) {
        int n = idx >> 4, kk = (idx & 15) << 3;
        *(uint4*)(&sW[n * KP2_ + kk]) = *(const uint4*)(&g_wt[0 * 16384 + n * 128 + kk]);
    }
    if (tid < 128) { sC1[tid] = g_C1[tid]; sC2[tid] = g_C2[tid]; sbw2[tid] = bw2[tid]; slog[tid] = 0.f; }
    float bb2v = bb2[0];

    // build X tile from etok (streaming) + row sums
    int row = tid >> 1, half = tid & 1;
    int e = tile * 128 + row;
    float s = 0.f, ss = 0.f;
    if (e < E_) {
        const float4* p = (const float4*)(etok + (size_t)e * H_ + half * 64);
        #pragma unroll
        for (int j = 0; j < 16; j++) {
            float4 v = p[j];
            s += v.x + v.y + v.z + v.w;
            ss += v.x * v.x + v.y * v.y + v.z * v.z + v.w * v.w;
            uint2 pk; pk.x = pack_bf2(v.x, v.y); pk.y = pack_bf2(v.z, v.w);
            *(uint2*)(&sX[row * KP2_ + half * 64 + j * 4]) = pk;
        }
    } else {
        #pragma unroll
        for (int j = 0; j < 16; j++)
            *(uint2*)(&sX[row * KP2_ + half * 64 + j * 4]) = make_uint2(0u, 0u);
    }
    float so = __shfl_xor_sync(0xffffffffu, s, 1);
    float sso = __shfl_xor_sync(0xffffffffu, ss, 1);
    if (half == 0) { sse1[row] = s + so; sse_[row] = ss + sso; }
    __syncthreads();

    // GEMM 128x128x128 (etok slab)
    unsigned sx_u = (unsigned)__cvta_generic_to_shared(sX);
    unsigned sw_u = (unsigned)__cvta_generic_to_shared(sW);
    int wm = w & 3, wn = w >> 2;
    int a_row = wm * 32 + (lane & 15);
    int a_k   = (lane >> 4) * 8;
    int b_nl  = wn * 64 + (lane & 7);
    int b_kl  = ((lane >> 3) & 1) * 8;

    float c[2][8][4];
    #pragma unroll
    for (int mt = 0; mt < 2; mt++)
        #pragma unroll
        for (int nt = 0; nt < 8; nt++)
            #pragma unroll
            for (int qi = 0; qi < 4; qi++) c[mt][nt][qi] = 0.f;

    #pragma unroll
    for (int ks = 0; ks < 8; ks++) {
        int k0 = ks * 16;
        unsigned af[2][4], bf[8][2];
        #pragma unroll
        for (int mt = 0; mt < 2; mt++)
            ldsm_x4(af[mt], sx_u + (unsigned)(((a_row + mt * 16) * KP2_ + k0 + a_k) * 2));
        #pragma unroll
        for (int nt = 0; nt < 8; nt++)
            ldsm_x2(bf[nt], sw_u + (unsigned)(((b_nl + nt * 8) * KP2_ + k0 + b_kl) * 2));
        #pragma unroll
        for (int mt = 0; mt < 2; mt++)
            #pragma unroll
            for (int nt = 0; nt < 8; nt++)
                mma16816(c[mt][nt], af[mt], bf[nt]);
    }
    __syncthreads();   // slog zero visible, X/W no longer needed

    // epilogue: add Uq[b] + Un[t] (bf16), LN affine, gelu, dot bw2
    #pragma unroll
    for (int mt = 0; mt < 2; mt++) {
        int r0 = wm * 32 + mt * 16 + (lane >> 2);
        int r1 = r0 + 8;
        int e0 = tile * 128 + r0, e1 = tile * 128 + r1;
        int ec0 = e0 < E_ ? e0 : E_ - 1;
        int ec1 = e1 < E_ ? e1 : E_ - 1;
        int b0 = ebatch[ec0], t0 = eindex[E_ + ec0];
        int b1 = ebatch[ec1], t1 = eindex[E_ + ec1];
        float mean0 = (sse1[r0] + g_sq[b0] + g_sn[t0]) * (1.f / 384.f);
        float msq0  = (sse_[r0] + g_ssq[b0] + g_ssn[t0]) * (1.f / 384.f);
        float rstd0 = rsqrtf(msq0 - mean0 * mean0 + 1e-5f);
        float mean1 = (sse1[r1] + g_sq[b1] + g_sn[t1]) * (1.f / 384.f);
        float msq1  = (sse_[r1] + g_ssq[b1] + g_ssn[t1]) * (1.f / 384.f);
        float rstd1 = rsqrtf(msq1 - mean1 * mean1 + 1e-5f);
        float acc0 = 0.f, acc1 = 0.f;
        #pragma unroll
        for (int nt = 0; nt < 8; nt++) {
            int col = wn * 64 + nt * 8 + (lane & 3) * 2;
            float c1a = sC1[col], c1b = sC1[col + 1];
            float c2a = sC2[col], c2b = sC2[col + 1];
            float w0 = sbw2[col], w1 = sbw2[col + 1];
            float2 uq0 = unpack_bf2(&g_Uq[b0 * H_ + col]);
            float2 un0 = unpack_bf2(&g_Un[(size_t)t0 * H_ + col]);
            float2 uq1 = unpack_bf2(&g_Uq[b1 * H_ + col]);
            float2 un1 = unpack_bf2(&g_Un[(size_t)t1 * H_ + col]);
            float h00 = rstd0 * (c[mt][nt][0] + uq0.x + un0.x - mean0 * c2a) + c1a;
            float h01 = rstd0 * (c[mt][nt][1] + uq0.y + un0.y - mean0 * c2b) + c1b;
            float h10 = rstd1 * (c[mt][nt][2] + uq1.x + un1.x - mean1 * c2a) + c1a;
            float h11 = rstd1 * (c[mt][nt][3] + uq1.y + un1.y - mean1 * c2b) + c1b;
            acc0 += gelu_f(h00) * w0 + gelu_f(h01) * w1;
            acc1 += gelu_f(h10) * w0 + gelu_f(h11) * w1;
        }
        // quad-reduce across the 4 lanes sharing this row, then 1 atomic per warp
        acc0 += __shfl_xor_sync(0xffffffffu, acc0, 1);
        acc0 += __shfl_xor_sync(0xffffffffu, acc0, 2);
        acc1 += __shfl_xor_sync(0xffffffffu, acc1, 1);
        acc1 += __shfl_xor_sync(0xffffffffu, acc1, 2);
        if ((lane & 3) == 0) {
            atomicAdd(&slog[r0], acc0);
            atomicAdd(&slog[r1], acc1);
        }
    }
    __syncthreads();
    if (tid < 128) {
        int ee = tile * 128 + tid;
        if (ee < E_) {
            float lv = slog[tid] + bb2v;
            g_logits[ee] = lv;
            atomicMaxF(&g_tmax[eindex[E_ + ee]], lv);  // fused segment-max
        }
    }
}

// ---------------- aggregate_start (segment softmax) ----------------
__global__ void k_start(const float* __restrict__ node, const float* __restrict__ q,
                        const int* __restrict__ locals, const int* __restrict__ ptr) {
    int g = blockIdx.x, j = threadIdx.x;
    __shared__ float red[128];
    __shared__ float sc[32];
    __shared__ int   nloc[32];
    int p0 = ptr[g], p1 = ptr[g + 1];
    int cnt = p1 - p0; if (cnt > 32) cnt = 32;
    if (cnt <= 0) { g_summary[g * H_ + j] = 0.f; return; }
    if (j < cnt) nloc[j] = locals[p0 + j];
    __syncthreads();
    float qj = q[g * H_ + j];
    for (int s = 0; s < cnt; s++) {
        red[j] = node[(size_t)nloc[s] * H_ + j] * qj;
        __syncthreads();
        for (int o = 64; o > 0; o >>= 1) { if (j < o) red[j] += red[j + o]; __syncthreads(); }
        if (j == 0) sc[s] = red[0] * 0.08838834764831845f;
        __syncthreads();
    }
    float m = -INFINITY;
    for (int s = 0; s < cnt; s++) m = fmaxf(m, sc[s]);
    float den = 0.f;
    for (int s = 0; s < cnt; s++) den += expf(sc[s] - m);
    float acc = 0.f;
    for (int s = 0; s < cnt; s++)
        acc += (expf(sc[s] - m) / den) * node[(size_t)nloc[s] * H_ + j];
    g_summary[g * H_ + j] = acc;
}

// ---------------- ctx_projector + log_z head ----------------
__global__ void k_ctx(const float* __restrict__ q,
                      const float* __restrict__ cw1, const float* __restrict__ cb1,
                      const float* __restrict__ cw2, const float* __restrict__ cb2,
                      const float* __restrict__ ln1g, const float* __restrict__ ln1b,
                      const float* __restrict__ zw1, const float* __restrict__ zb1,
                      const float* __restrict__ zw2, const float* __restrict__ zb2) {
    int g = blockIdx.x, j = threadIdx.x;
    __shared__ float s_in[256];
    __shared__ float sv[128];
    __shared__ float red[128];
    __shared__ float bc;
    s_in[j]       = g_summary[g * H_ + j];
    s_in[H_ + j]  = q[g * H_ + j];
    __syncthreads();
    float h = cb1[j];
    #pragma unroll 4
    for (int k = 0; k < 2 * H_; k++) h += s_in[k] * cw1[k * H_ + j];
    float a = gelu_f(h);
    sv[j] = a;
    __syncthreads();
    float ctx = cb2[j];
    #pragma unroll 4
    for (int k = 0; k < H_; k++) ctx += sv[k] * cw2[k * H_ + j];
    red[j] = ctx; __syncthreads();
    for (int o = 64; o > 0; o >>= 1) { if (j < o) red[j] += red[j + o]; __syncthreads(); }
    if (j == 0) bc = red[0];
    __syncthreads();
    float mean = bc * (1.f / 128.f);
    float d = ctx - mean;
    red[j] = d * d; __syncthreads();
    for (int o = 64; o > 0; o >>= 1) { if (j < o) red[j] += red[j + o]; __syncthreads(); }
    if (j == 0) bc = red[0];
    __syncthreads();
    float rstd = rsqrtf(bc * (1.f / 128.f) + 1e-5f);
    float xh = d * rstd * ln1g[j] + ln1b[j];
    __syncthreads();
    sv[j] = xh;
    __syncthreads();
    float z = zb1[j];
    #pragma unroll 4
    for (int k = 0; k < H_; k++) z += sv[k] * zw1[k * H_ + j];
    float gz = gelu_f(z);
    red[j] = gz * zw2[j];
    __syncthreads();
    for (int o = 64; o > 0; o >>= 1) { if (j < o) red[j] += red[j + o]; __syncthreads(); }
    if (j == 0) g_logz[g] = red[0] + zb2[0];
}

// ---------------- segment log-softmax denom / lse / per-graph accumulation --------------
__global__ void k_nodedenom(const int* __restrict__ eindex) {
    int e = blockIdx.x * blockDim.x + threadIdx.x;
    if (e >= E_) return;
    int t = eindex[E_ + e];
    atomicAdd(&g_denom[t], expf(g_logits[e] - g_tmax[t]));
}

__global__ void k_lse() {
    int t = blockIdx.x * blockDim.x + threadIdx.x;
    if (t >= NN_) return;
    g_denom[t] = g_tmax[t] + logf(g_denom[t]);
}

__global__ void k_accum(const int* __restrict__ eindex, const int* __restrict__ ebatch,
                        const void* __restrict__ mask) {
    int e = blockIdx.x * blockDim.x + threadIdx.x;
    if (e >= E_) return;
    bool sel;
    if (g_flags[0])      sel = (((const float*)mask)[e] != 0.f);
    else if (g_flags[1]) sel = (((const unsigned char*)mask)[e] != 0);
    else                 sel = (((const int*)mask)[e] != 0);
    if (sel) {
        int t = eindex[E_ + e];
        float lp = g_logits[e] - g_denom[t];
        int b = ebatch[e];
        atomicAdd(&g_lpb[b], lp);
        atomicAdd(&g_cnt[b], 1.f);
    }
}

// ---------------- finalize + write output [G,3] ----------------
__global__ void k_final(float* __restrict__ out) {
    int g = threadIdx.x;   // 1024 threads
    float cnt = g_cnt[g], lpb = g_lpb[g];
    float has = cnt > 0.f ? 1.f : 0.f;
    float nll = -lpb * has;
    __shared__ float s_n[32], s_h[32];
    __shared__ float s_pb;
    float n2 = nll, h2 = has;
    #pragma unroll
    for (int o = 16; o > 0; o >>= 1) {
        n2 += __shfl_xor_sync(0xffffffffu, n2, o);
        h2 += __shfl_xor_sync(0xffffffffu, h2, o);
    }
    if ((g & 31) == 0) { s_n[g >> 5] = n2; s_h[g >> 5] = h2; }
    __syncthreads();
    if (g < 32) {
        float a = s_n[g], b = s_h[g];
        #pragma unroll
        for (int o = 16; o > 0; o >>= 1) {
            a += __shfl_xor_sync(0xffffffffu, a, o);
            b += __shfl_xor_sync(0xffffffffu, b, o);
        }
        if (g == 0) s_pb = a / fmaxf(b, 1.f);
    }
    __syncthreads();
    out[g * 3 + 0] = g_logz[g];
    out[g * 3 + 1] = lpb;
    out[g * 3 + 2] = s_pb;
}

// ---------------- launch ----------------
extern "C" void kernel_launch(void* const* d_in, const int* in_sizes, int n_in,
                              void* d_out, int out_size) {
    int I_node, I_q, I_etok, I_loc, I_ptr, I_ebatch, I_mask, I_eidx,
        I_ln1g, I_ln1b, I_zw1, I_zb1, I_zw2, I_zb2, I_cw1, I_cb1, I_cw2, I_cb2,
        I_blng, I_blnb, I_bw1, I_bb1, I_bw2, I_bb2;
    if (in_sizes[3] == 4096) {   // setup_inputs dict order
        I_node = 0;  I_q = 1;    I_etok = 2;  I_loc = 3;  I_ptr = 4;
        I_ebatch = 5; I_mask = 6; I_eidx = 7;
        I_ln1g = 8;  I_ln1b = 9; I_zw1 = 10;  I_zb1 = 11; I_zw2 = 12; I_zb2 = 13;
        I_cw1 = 14;  I_cb1 = 15; I_cw2 = 16;  I_cb2 = 17;
        I_blng = 18; I_blnb = 19; I_bw1 = 20; I_bb1 = 21; I_bw2 = 22; I_bb2 = 23;
    } else {                     // reference signature order
        I_node = 0;  I_q = 1;    I_etok = 2;
        I_ln1g = 3;  I_ln1b = 4; I_zw1 = 5;   I_zb1 = 6;  I_zw2 = 7;  I_zb2 = 8;
        I_cw1 = 9;   I_cb1 = 10; I_cw2 = 11;  I_cb2 = 12;
        I_blng = 13; I_blnb = 14; I_bw1 = 15; I_bb1 = 16; I_bw2 = 17; I_bb2 = 18;
        I_loc = 19;  I_ptr = 20; I_ebatch = 21; I_mask = 22; I_eidx = 23;
    }

    const float* node  = (const float*)d_in[I_node];
    const float* q     = (const float*)d_in[I_q];
    const float* etok  = (const float*)d_in[I_etok];
    const int*   loc   = (const int*)d_in[I_loc];
    const int*   ptr   = (const int*)d_in[I_ptr];
    const int*   ebat  = (const int*)d_in[I_ebatch];
    const int*   eidx  = (const int*)d_in[I_eidx];
    const float* ln1g  = (const float*)d_in[I_ln1g];
    const float* ln1b  = (const float*)d_in[I_ln1b];
    const float* zw1   = (const float*)d_in[I_zw1];
    const float* zb1   = (const float*)d_in[I_zb1];
    const float* zw2   = (const float*)d_in[I_zw2];
    const float* zb2   = (const float*)d_in[I_zb2];
    const float* cw1   = (const float*)d_in[I_cw1];
    const float* cb1   = (const float*)d_in[I_cb1];
    const float* cw2   = (const float*)d_in[I_cw2];
    const float* cb2   = (const float*)d_in[I_cb2];
    const float* blng  = (const float*)d_in[I_blng];
    const float* blnb  = (const float*)d_in[I_blnb];
    const float* bw1   = (const float*)d_in[I_bw1];
    const float* bb1   = (const float*)d_in[I_bb1];
    const float* bw2   = (const float*)d_in[I_bw2];
    const float* bb2   = (const float*)d_in[I_bb2];

    const int SM_ROWG = 2 * 128 * KP2_ * 2;            // 69632
    const int SM_UE   = SM_ROWG + 6 * 128 * 4;         // 72704
    cudaFuncSetAttribute(k_rowgemm, cudaFuncAttributeMaxDynamicSharedMemorySize, SM_ROWG);
    cudaFuncSetAttribute(k_ue,      cudaFuncAttributeMaxDynamicSharedMemorySize, SM_UE);

    k_init<<<(NN_ + 255) / 256, 256>>>();
    k_detect<<<(E_ / 4 + 255) / 256, 256>>>((const unsigned*)d_in[I_mask]);
    k_prep<<<(3 * 128 * 128 + 255) / 256, 256>>>(bw1, blng);
    k_prepc<<<128, 128>>>(bw1, blng, blnb, bb1);
    k_rowgemm<<<NTILE_N, 256, SM_ROWG>>>(node, NN_, 2, 0);
    k_rowgemm<<<NTILE_Q, 256, SM_ROWG>>>(q, G_, 1, 1);
    k_start<<<G_, 128>>>(node, q, loc, ptr);
    k_ctx<<<G_, 128>>>(q, cw1, cb1, cw2, cb2, ln1g, ln1b, zw1, zb1, zw2, zb2);
    k_ue<<<NTILE_E, 256, SM_UE>>>(etok, bw2, bb2, ebat, eidx);
    k_nodedenom<<<(E_ + 255) / 256, 256>>>(eidx);
    k_lse<<<(NN_ + 255) / 256, 256>>>();
    k_accum<<<(E_ + 255) / 256, 256>>>(eidx, ebat, d_in[I_mask]);
    k_final<<<1, 1024>>>((float*)d_out);
}